// round 12
// baseline (speedup 1.0000x reference)
#include <cuda_runtime.h>

#define NB   1024   // assets
#define NT   4096   // timesteps
#define NH   20     // hidden

__device__ float g_hlast[NB * NH];

using u64 = unsigned long long;

__device__ __forceinline__ u64 pack2(float lo, float hi) {
    u64 r;
    asm("mov.b64 %0, {%1, %2};" : "=l"(r)
        : "r"(__float_as_uint(lo)), "r"(__float_as_uint(hi)));
    return r;
}
__device__ __forceinline__ float2 unpack2(u64 v) {
    unsigned lo, hi;
    asm("mov.b64 {%0, %1}, %2;" : "=r"(lo), "=r"(hi) : "l"(v));
    return make_float2(__uint_as_float(lo), __uint_as_float(hi));
}
__device__ __forceinline__ u64 ffma2(u64 a, u64 b, u64 c) {
    u64 d;
    asm("fma.rn.f32x2 %0, %1, %2, %3;" : "=l"(d) : "l"(a), "l"(b), "l"(c));
    return d;
}
__device__ __forceinline__ u64 add2(u64 a, u64 b) {
    u64 d;
    asm("add.rn.f32x2 %0, %1, %2;" : "=l"(d) : "l"(a), "l"(b));
    return d;
}
__device__ __forceinline__ float tanha(float x) {
    float y; asm("tanh.approx.f32 %0, %1;" : "=f"(y) : "f"(x)); return y;
}

// ============================================================================
// R5 instruction set, rescheduled:
//   step t: SYNC -> LDS hk[0..7] (h(t-1)[0..15]) -> secondary block processes
//   act4p=act[4](t-1) into hk[8..9]=h(t-1)[16..19] (fills LDS window) ->
//   slot-sequential chains (hk[8..9] at TAILS, reached ~140cy later) with
//   inline activations -> shadow ini(t+1) -> c1/h1 -> STS -> act4p=act[4].
// 2 assets per warp; half = l>>4, q = l&15, asset = 2*bid + half.
// Lane q slots s=0..3: gate 20*s+q == unit q's i,f,g,o (lane-local).
// Slot s=4: gate 20*(q&3) + 16 + (q>>2)  (unit 16+(q>>2), type q&3).
// Sigmoid via 0.5*tanh(x/2)+0.5 (0.5 folded into weights); g-gate raw tanh.
// ============================================================================
__global__ void __launch_bounds__(32)
lstm_kernel(const float* __restrict__ x,
            const float* __restrict__ Wih,
            const float* __restrict__ Whh,
            const float* __restrict__ bih,
            const float* __restrict__ bhh)
{
    const int l  = threadIdx.x;
    const int q  = l & 15;
    const int hb = l & 16;
    const int half = l >> 4;
    const int asset = 2 * blockIdx.x + half;

    __shared__ __align__(16) float s_h[2][2][16];   // [buf][half][unit 0..15]

    // ---- per-slot constants ----
    u64 wS[5][10], wi01[5], wi2z[5], bia[5];
    int gate[5];
#pragma unroll
    for (int s = 0; s < 4; s++) gate[s] = 20 * s + q;
    gate[4] = 20 * (q & 3) + 16 + (q >> 2);
    const bool t4 = ((q & 3) == 2);
    const float aa4 = t4 ? 1.0f : 0.5f;
    const float ab4 = t4 ? 0.0f : 0.5f;
#pragma unroll
    for (int s = 0; s < 5; s++) {
        const int g = gate[s];
        const bool tg = (s == 2) || (s == 4 && t4);
        const float sc = tg ? 1.0f : 0.5f;
        const float2* rw = reinterpret_cast<const float2*>(Whh + g * NH);
#pragma unroll
        for (int k = 0; k < 10; k++) {
            float2 v = rw[k];
            wS[s][k] = pack2(sc * v.x, sc * v.y);
        }
        wi01[s] = pack2(sc * Wih[g*3+0], sc * Wih[g*3+1]);
        wi2z[s] = pack2(sc * Wih[g*3+2], 0.f);
        bia[s]  = pack2(sc * (bih[g] + bhh[g]), 0.f);
    }
    const u64 ZZ = 0ull;

    // secondary gather sources: unit 16+q's type m comes from lane hb|(4q+m)
    const int sI = hb | ((4 * q + 0) & 15);
    const int sF = hb | ((4 * q + 1) & 15);
    const int sG = hb | ((4 * q + 2) & 15);
    const int sO = hb | ((4 * q + 3) & 15);

    // ---- x pointers: x[f][asset][t], float4 groups ----
    const float4* p0 = reinterpret_cast<const float4*>(x + (size_t)asset * NT);
    const float4* p1 = p0 + (size_t)NB * NT / 4;
    const float4* p2 = p1 + (size_t)NB * NT / 4;

    float4 cx0 = p0[0], cx1 = p1[0], cx2 = p2[0];

    // bootstrap: h(-1)=0 in buffer 0; c,act4p zero
    if (q < 16) s_h[0][half][q] = 0.f;
    float c1 = 0.f, c2 = 0.f, h1 = 0.f, h2 = 0.f;
    float act4p = 0.f;          // act[4] of previous step (0 -> h2 stays 0)

    u64 hk[10];
#pragma unroll
    for (int k = 0; k < 10; k++) hk[k] = 0ull;

    // step 0 chain bases (bias + x-part of t=0)
    u64 iniA[5], iniB[5];
    {
        const u64 x01 = pack2(cx0.x, cx1.x);
        const u64 x22 = pack2(cx2.x, cx2.x);
#pragma unroll
        for (int s = 0; s < 5; s++) {
            iniA[s] = ffma2(x01, wi01[s], bia[s]);
            iniB[s] = ffma2(x22, wi2z[s], ZZ);
        }
    }

    // Xn* = x of the NEXT step; rbuf = buffer holding h(t-1)[0..15]
    auto step = [&](float Xn0, float Xn1, float Xn2, int rbuf) {
        __syncwarp();

        // h(t-1)[0..15] from smem (4x LDS.128, broadcast, conflict-free)
        const ulonglong2* hp = reinterpret_cast<const ulonglong2*>(s_h[rbuf][half]);
        ulonglong2 r;
        r = hp[0]; hk[0] = r.x; hk[1] = r.y;
        r = hp[1]; hk[2] = r.x; hk[3] = r.y;
        r = hp[2]; hk[4] = r.x; hk[5] = r.y;
        r = hp[3]; hk[6] = r.x; hk[7] = r.y;

        // secondary block: act4p = act[4](t-1) -> h(t-1)[16..19] = hk[8..9].
        // Issues in the LDS latency window; consumed only at the chain tails.
        {
            const float i2 = __shfl_sync(0xffffffffu, act4p, sI);
            const float f2 = __shfl_sync(0xffffffffu, act4p, sF);
            const float g2 = __shfl_sync(0xffffffffu, act4p, sG);
            const float o2 = __shfl_sync(0xffffffffu, act4p, sO);
            c2 = fmaf(f2, c2, i2 * g2);
            h2 = o2 * tanha(c2);
            hk[8] = pack2(__shfl_sync(0xffffffffu, h2, hb | 0),
                          __shfl_sync(0xffffffffu, h2, hb | 1));
            hk[9] = pack2(__shfl_sync(0xffffffffu, h2, hb | 2),
                          __shfl_sync(0xffffffffu, h2, hb | 3));
        }

        // slot-SEQUENTIAL chains with inline activations; hk[8..9] at tails
        float act[5];
#pragma unroll
        for (int s = 0; s < 5; s++) {
            u64 A = ffma2(hk[0], wS[s][0], iniA[s]);
            u64 B = ffma2(hk[1], wS[s][1], iniB[s]);
            A = ffma2(hk[2], wS[s][2], A);
            B = ffma2(hk[3], wS[s][3], B);
            A = ffma2(hk[4], wS[s][4], A);
            B = ffma2(hk[5], wS[s][5], B);
            A = ffma2(hk[6], wS[s][6], A);
            B = ffma2(hk[7], wS[s][7], B);
            A = ffma2(hk[8], wS[s][8], A);
            B = ffma2(hk[9], wS[s][9], B);
            float2 p = unpack2(add2(A, B));
            const float th = tanha(p.x + p.y);
            act[s] = (s == 2) ? th
                   : (s == 4) ? fmaf(aa4, th, ab4)
                              : fmaf(0.5f, th, 0.5f);
        }

        // next step's chain bases: issue during the activation tanh waits
        const u64 x01n = pack2(Xn0, Xn1);
        const u64 x22n = pack2(Xn2, Xn2);
#pragma unroll
        for (int s = 0; s < 5; s++) {
            iniA[s] = ffma2(x01n, wi01[s], bia[s]);
            iniB[s] = ffma2(x22n, wi2z[s], ZZ);
        }

        // primary tail
        c1 = fmaf(act[1], c1, act[0] * act[2]);
        h1 = act[3] * tanha(c1);
        s_h[rbuf ^ 1][half][q] = h1;   // write the OTHER buffer
        act4p = act[4];                // processed at the top of next step
    };

#pragma unroll 1
    for (int t4i = 0; t4i < NT/4 - 1; t4i++) {
        const float4 nx0 = p0[t4i + 1];
        const float4 nx1 = p1[t4i + 1];
        const float4 nx2 = p2[t4i + 1];
        step(cx0.y, cx1.y, cx2.y, 0);
        step(cx0.z, cx1.z, cx2.z, 1);
        step(cx0.w, cx1.w, cx2.w, 0);
        step(nx0.x, nx1.x, nx2.x, 1);
        cx0 = nx0; cx1 = nx1; cx2 = nx2;
    }
    // last group: next-x args are don't-cares (reuse current)
    step(cx0.y, cx1.y, cx2.y, 0);
    step(cx0.z, cx1.z, cx2.z, 1);
    step(cx0.w, cx1.w, cx2.w, 0);
    step(cx0.w, cx1.w, cx2.w, 1);

    // final secondary pass: h(T-1)[16..19] from the last step's act[4]
    {
        const float i2 = __shfl_sync(0xffffffffu, act4p, sI);
        const float f2 = __shfl_sync(0xffffffffu, act4p, sF);
        const float g2 = __shfl_sync(0xffffffffu, act4p, sG);
        const float o2 = __shfl_sync(0xffffffffu, act4p, sO);
        c2 = fmaf(f2, c2, i2 * g2);
        h2 = o2 * tanha(c2);
    }

    g_hlast[asset * NH + q] = h1;                 // units 0..15
    if (q < 4) g_hlast[asset * NH + 16 + q] = h2; // units 16..19
}

// head: fc + 1x1 conv compose linearly: z_b = cw0*la_b + relu(h_b)·u + s
__global__ void __launch_bounds__(NB)
head_kernel(const float* __restrict__ la,
            const float* __restrict__ fcw,
            const float* __restrict__ fcb,
            const float* __restrict__ cw,
            const float* __restrict__ cb,
            float* __restrict__ out)
{
    const int b = threadIdx.x;
    __shared__ float s_u[NH];
    __shared__ float s_s;
    __shared__ float s_red[32];
    __shared__ float s_bcast;

    if (b < NH) {
        float u = 0.f;
#pragma unroll
        for (int j = 0; j < NH; j++) u = fmaf(cw[1 + j], fcw[j * NH + b], u);
        s_u[b] = u;
    }
    if (b == NH) {
        float s = cb[0];
#pragma unroll
        for (int j = 0; j < NH; j++) s = fmaf(cw[1 + j], fcb[j], s);
        s_s = s;
    }
    __syncthreads();

    float z = fmaf(cw[0], la[b], s_s);
    const float* h = &g_hlast[b * NH];
#pragma unroll
    for (int j = 0; j < NH; j++) z = fmaf(fmaxf(h[j], 0.f), s_u[j], z);

    float m = z;
#pragma unroll
    for (int off = 16; off > 0; off >>= 1)
        m = fmaxf(m, __shfl_xor_sync(0xffffffffu, m, off));
    if ((b & 31) == 0) s_red[b >> 5] = m;
    __syncthreads();
    if (b < 32) {
        float v = s_red[b];
#pragma unroll
        for (int off = 16; off > 0; off >>= 1)
            v = fmaxf(v, __shfl_xor_sync(0xffffffffu, v, off));
        if (b == 0) s_bcast = fmaxf(v, 1.0f);
    }
    __syncthreads();
    m = s_bcast;

    float e = __expf(z - m);
    float s = e;
#pragma unroll
    for (int off = 16; off > 0; off >>= 1)
        s += __shfl_xor_sync(0xffffffffu, s, off);
    if ((b & 31) == 0) s_red[b >> 5] = s;
    __syncthreads();
    if (b < 32) {
        float v = s_red[b];
#pragma unroll
        for (int off = 16; off > 0; off >>= 1)
            v += __shfl_xor_sync(0xffffffffu, v, off);
        if (b == 0) s_bcast = v + __expf(1.0f - m);
    }
    __syncthreads();
    const float denom = s_bcast;

    out[1 + b] = e / denom;
    if (b == 0) out[0] = __expf(1.0f - m) / denom;
}

extern "C" void kernel_launch(void* const* d_in, const int* in_sizes, int n_in,
                              void* d_out, int out_size)
{
    const float* x   = (const float*)d_in[0];
    const float* la  = (const float*)d_in[1];
    const float* Wih = (const float*)d_in[2];
    const float* Whh = (const float*)d_in[3];
    const float* bih = (const float*)d_in[4];
    const float* bhh = (const float*)d_in[5];
    const float* fcw = (const float*)d_in[6];
    const float* fcb = (const float*)d_in[7];
    const float* cw  = (const float*)d_in[8];
    const float* cb  = (const float*)d_in[9];

    lstm_kernel<<<NB / 2, 32>>>(x, Wih, Whh, bih, bhh);
    head_kernel<<<1, NB>>>(la, fcw, fcb, cw, cb, (float*)d_out);
}

// round 13
// speedup vs baseline: 1.2913x; 1.2913x over previous
#include <cuda_runtime.h>
#include <cuda_fp16.h>

#define NB   1024   // assets
#define NT   4096   // timesteps
#define NH   20     // hidden

__device__ float g_hlast[NB * NH];

using u64 = unsigned long long;

__device__ __forceinline__ u64 pack2(float lo, float hi) {
    u64 r;
    asm("mov.b64 %0, {%1, %2};" : "=l"(r)
        : "r"(__float_as_uint(lo)), "r"(__float_as_uint(hi)));
    return r;
}
__device__ __forceinline__ float2 unpack2(u64 v) {
    unsigned lo, hi;
    asm("mov.b64 {%0, %1}, %2;" : "=r"(lo), "=r"(hi) : "l"(v));
    return make_float2(__uint_as_float(lo), __uint_as_float(hi));
}
__device__ __forceinline__ u64 ffma2(u64 a, u64 b, u64 c) {
    u64 d;
    asm("fma.rn.f32x2 %0, %1, %2, %3;" : "=l"(d) : "l"(a), "l"(b), "l"(c));
    return d;
}
__device__ __forceinline__ float tanha(float x) {
    float y; asm("tanh.approx.f32 %0, %1;" : "=f"(y) : "f"(x)); return y;
}

// ============================================================================
// R5 skeleton (best: 570us). ONLY change: the recurrent 20-dot runs in fp16
// via HFMA2 (rt 2 — three 32-bit operands beat ffma2's 3-even/3-odd rt-3
// banking), h exchanged through smem as fp16. ini (x-part+bias) and all
// state math stay fp32; c1/c2 never touch fp16.
// 2 assets per warp; half = l>>4, q = l&15, asset = 2*bid + half.
// Lane q slots s=0..3: gate 20*s+q == unit q's i,f,g,o (lane-local).
// Slot s=4: gate 20*(q&3) + 16 + (q>>2)  (unit 16+(q>>2), type q&3).
// Sigmoid via 0.5*tanh(x/2)+0.5 (0.5 folded into weights); g-gate raw tanh.
// ============================================================================
__global__ void __launch_bounds__(32)
lstm_kernel(const float* __restrict__ x,
            const float* __restrict__ Wih,
            const float* __restrict__ Whh,
            const float* __restrict__ bih,
            const float* __restrict__ bhh)
{
    const int l  = threadIdx.x;
    const int q  = l & 15;
    const int hb = l & 16;
    const int half = l >> 4;
    const int asset = 2 * blockIdx.x + half;

    // h exchange in fp16: [buf][half][32 halves] (units 0..15 used = 32B)
    __shared__ __align__(16) __half s_h[2][2][32];

    // ---- per-slot constants ----
    __half2 wH[5][10];                 // W_hh rows, scaled, K-packed fp16
    int gate[5];
#pragma unroll
    for (int s = 0; s < 4; s++) gate[s] = 20 * s + q;
    gate[4] = 20 * (q & 3) + 16 + (q >> 2);
    const bool t4 = ((q & 3) == 2);
    const float aa4 = t4 ? 1.0f : 0.5f;
    const float ab4 = t4 ? 0.0f : 0.5f;
    float sc[5];
#pragma unroll
    for (int s = 0; s < 5; s++) {
        const bool tg = (s == 2) || (s == 4 && t4);
        sc[s] = tg ? 1.0f : 0.5f;
        const float2* rw = reinterpret_cast<const float2*>(Whh + gate[s] * NH);
#pragma unroll
        for (int k = 0; k < 10; k++) {
            float2 v = rw[k];
            wH[s][k] = __floats2half2_rn(sc[s] * v.x, sc[s] * v.y);
        }
    }
    // ini as slot-pairs (s0,s1),(s2,s3),(s4,junk): complete scalars per slot
    u64 wiP0[3], wiP1[3], wiP2[3], biaP[3];
#pragma unroll
    for (int p = 0; p < 3; p++) {
        const int sA = 2 * p;
        const int sB = (p < 2) ? (2 * p + 1) : 4;   // p=2: (s4, s4-dup harmless)
        const int gA = gate[sA], gB = gate[(p < 2) ? sB : 4];
        const float cA = sc[sA], cB = (p < 2) ? sc[sB] : 0.f;
        wiP0[p] = pack2(cA * Wih[gA*3+0], cB * Wih[gB*3+0]);
        wiP1[p] = pack2(cA * Wih[gA*3+1], cB * Wih[gB*3+1]);
        wiP2[p] = pack2(cA * Wih[gA*3+2], cB * Wih[gB*3+2]);
        biaP[p] = pack2(cA * (bih[gA] + bhh[gA]), cB * (bih[gB] + bhh[gB]));
    }
    // p=2 lo-half is s4; fix its sources properly
    {
        const int g4 = gate[4];
        wiP0[2] = pack2(sc[4] * Wih[g4*3+0], 0.f);
        wiP1[2] = pack2(sc[4] * Wih[g4*3+1], 0.f);
        wiP2[2] = pack2(sc[4] * Wih[g4*3+2], 0.f);
        biaP[2] = pack2(sc[4] * (bih[g4] + bhh[g4]), 0.f);
    }

    // secondary gather sources: unit 16+q's type m comes from lane hb|(4q+m)
    const int sI = hb | ((4 * q + 0) & 15);
    const int sF = hb | ((4 * q + 1) & 15);
    const int sG = hb | ((4 * q + 2) & 15);
    const int sO = hb | ((4 * q + 3) & 15);

    // ---- x pointers: x[f][asset][t], float4 groups ----
    const float4* p0 = reinterpret_cast<const float4*>(x + (size_t)asset * NT);
    const float4* p1 = p0 + (size_t)NB * NT / 4;
    const float4* p2 = p1 + (size_t)NB * NT / 4;

    float4 cx0 = p0[0], cx1 = p1[0], cx2 = p2[0];

    __half2 hk[10];
    const __half2 Z2 = __floats2half2_rn(0.f, 0.f);
#pragma unroll
    for (int k = 0; k < 10; k++) hk[k] = Z2;
    float c1 = 0.f, c2 = 0.f, h1 = 0.f, h2 = 0.f;

    // first step's ini scalars (bias + x-part of t=0), fp32
    float ini[5];
    {
        const u64 xx0 = pack2(cx0.x, cx0.x);
        const u64 xx1 = pack2(cx1.x, cx1.x);
        const u64 xx2 = pack2(cx2.x, cx2.x);
#pragma unroll
        for (int p = 0; p < 3; p++) {
            u64 ip = ffma2(xx0, wiP0[p],
                      ffma2(xx1, wiP1[p],
                       ffma2(xx2, wiP2[p], biaP[p])));
            float2 f = unpack2(ip);
            if (p < 2) { ini[2*p] = f.x; ini[2*p+1] = f.y; }
            else       { ini[4] = f.x; }
        }
    }

    // Xn* = x of the NEXT step (for the shadow init)
    auto step = [&](float Xn0, float Xn1, float Xn2, int buf) {
        // two 5-deep HFMA2 chains per slot; heads on register-resident
        // hk[8..9], then hk[0..7] in LDS arrival order
        float act[5];
#pragma unroll
        for (int s = 0; s < 5; s++) {
            __half2 A = __hmul2(hk[8], wH[s][8]);
            __half2 B = __hmul2(hk[9], wH[s][9]);
            A = __hfma2(hk[0], wH[s][0], A);
            B = __hfma2(hk[1], wH[s][1], B);
            A = __hfma2(hk[2], wH[s][2], A);
            B = __hfma2(hk[3], wH[s][3], B);
            A = __hfma2(hk[4], wH[s][4], A);
            B = __hfma2(hk[5], wH[s][5], B);
            A = __hfma2(hk[6], wH[s][6], A);
            B = __hfma2(hk[7], wH[s][7], B);
            float2 pf = __half22float2(__hadd2(A, B));
            const float pre = pf.x + pf.y + ini[s];
            const float th = tanha(pre);
            act[s] = (s == 2) ? th
                   : (s == 4) ? fmaf(aa4, th, ab4)
                              : fmaf(0.5f, th, 0.5f);
        }

        // secondary gather (register shuffles, off the primary path)
        const float i2 = __shfl_sync(0xffffffffu, act[4], sI);
        const float f2 = __shfl_sync(0xffffffffu, act[4], sF);
        const float g2 = __shfl_sync(0xffffffffu, act[4], sG);
        const float o2 = __shfl_sync(0xffffffffu, act[4], sO);

        // primary update: fully lane-local; h stored to smem as fp16
        c1 = fmaf(act[1], c1, act[0] * act[2]);
        h1 = act[3] * tanha(c1);
        s_h[buf][half][q] = __float2half_rn(h1);

        // secondary update + distribution into hk[8..9] (inputs ready here)
        c2 = fmaf(f2, c2, i2 * g2);
        h2 = o2 * tanha(c2);
        hk[8] = __floats2half2_rn(__shfl_sync(0xffffffffu, h2, hb | 0),
                                  __shfl_sync(0xffffffffu, h2, hb | 1));
        hk[9] = __floats2half2_rn(__shfl_sync(0xffffffffu, h2, hb | 2),
                                  __shfl_sync(0xffffffffu, h2, hb | 3));

        // next step's ini in the sync shadow (fp32)
        const u64 xx0 = pack2(Xn0, Xn0);
        const u64 xx1 = pack2(Xn1, Xn1);
        const u64 xx2 = pack2(Xn2, Xn2);
#pragma unroll
        for (int p = 0; p < 3; p++) {
            u64 ip = ffma2(xx0, wiP0[p],
                      ffma2(xx1, wiP1[p],
                       ffma2(xx2, wiP2[p], biaP[p])));
            float2 f = unpack2(ip);
            if (p < 2) { ini[2*p] = f.x; ini[2*p+1] = f.y; }
            else       { ini[4] = f.x; }
        }

        __syncwarp();

        // hk[0..7] from smem (2x LDS.128 of fp16 h, broadcast, conflict-free)
        const uint4* hp = reinterpret_cast<const uint4*>(s_h[buf][half]);
        uint4 r0 = hp[0];
        uint4 r1 = hp[1];
        hk[0] = *reinterpret_cast<__half2*>(&r0.x);
        hk[1] = *reinterpret_cast<__half2*>(&r0.y);
        hk[2] = *reinterpret_cast<__half2*>(&r0.z);
        hk[3] = *reinterpret_cast<__half2*>(&r0.w);
        hk[4] = *reinterpret_cast<__half2*>(&r1.x);
        hk[5] = *reinterpret_cast<__half2*>(&r1.y);
        hk[6] = *reinterpret_cast<__half2*>(&r1.z);
        hk[7] = *reinterpret_cast<__half2*>(&r1.w);
    };

#pragma unroll 1
    for (int t4i = 0; t4i < NT/4 - 1; t4i++) {
        const float4 nx0 = p0[t4i + 1];
        const float4 nx1 = p1[t4i + 1];
        const float4 nx2 = p2[t4i + 1];
        step(cx0.y, cx1.y, cx2.y, 0);
        step(cx0.z, cx1.z, cx2.z, 1);
        step(cx0.w, cx1.w, cx2.w, 0);
        step(nx0.x, nx1.x, nx2.x, 1);
        cx0 = nx0; cx1 = nx1; cx2 = nx2;
    }
    // last group: next-x args are don't-cares (reuse current)
    step(cx0.y, cx1.y, cx2.y, 0);
    step(cx0.z, cx1.z, cx2.z, 1);
    step(cx0.w, cx1.w, cx2.w, 0);
    step(cx0.w, cx1.w, cx2.w, 1);

    g_hlast[asset * NH + q] = h1;                 // units 0..15 (full fp32)
    if (q < 4) g_hlast[asset * NH + 16 + q] = h2; // units 16..19
}

// head: fc + 1x1 conv compose linearly: z_b = cw0*la_b + relu(h_b)·u + s
__global__ void __launch_bounds__(NB)
head_kernel(const float* __restrict__ la,
            const float* __restrict__ fcw,
            const float* __restrict__ fcb,
            const float* __restrict__ cw,
            const float* __restrict__ cb,
            float* __restrict__ out)
{
    const int b = threadIdx.x;
    __shared__ float s_u[NH];
    __shared__ float s_s;
    __shared__ float s_red[32];
    __shared__ float s_bcast;

    if (b < NH) {
        float u = 0.f;
#pragma unroll
        for (int j = 0; j < NH; j++) u = fmaf(cw[1 + j], fcw[j * NH + b], u);
        s_u[b] = u;
    }
    if (b == NH) {
        float s = cb[0];
#pragma unroll
        for (int j = 0; j < NH; j++) s = fmaf(cw[1 + j], fcb[j], s);
        s_s = s;
    }
    __syncthreads();

    float z = fmaf(cw[0], la[b], s_s);
    const float* h = &g_hlast[b * NH];
#pragma unroll
    for (int j = 0; j < NH; j++) z = fmaf(fmaxf(h[j], 0.f), s_u[j], z);

    float m = z;
#pragma unroll
    for (int off = 16; off > 0; off >>= 1)
        m = fmaxf(m, __shfl_xor_sync(0xffffffffu, m, off));
    if ((b & 31) == 0) s_red[b >> 5] = m;
    __syncthreads();
    if (b < 32) {
        float v = s_red[b];
#pragma unroll
        for (int off = 16; off > 0; off >>= 1)
            v = fmaxf(v, __shfl_xor_sync(0xffffffffu, v, off));
        if (b == 0) s_bcast = fmaxf(v, 1.0f);
    }
    __syncthreads();
    m = s_bcast;

    float e = __expf(z - m);
    float s = e;
#pragma unroll
    for (int off = 16; off > 0; off >>= 1)
        s += __shfl_xor_sync(0xffffffffu, s, off);
    if ((b & 31) == 0) s_red[b >> 5] = s;
    __syncthreads();
    if (b < 32) {
        float v = s_red[b];
#pragma unroll
        for (int off = 16; off > 0; off >>= 1)
            v += __shfl_xor_sync(0xffffffffu, v, off);
        if (b == 0) s_bcast = v + __expf(1.0f - m);
    }
    __syncthreads();
    const float denom = s_bcast;

    out[1 + b] = e / denom;
    if (b == 0) out[0] = __expf(1.0f - m) / denom;
}

extern "C" void kernel_launch(void* const* d_in, const int* in_sizes, int n_in,
                              void* d_out, int out_size)
{
    const float* x   = (const float*)d_in[0];
    const float* la  = (const float*)d_in[1];
    const float* Wih = (const float*)d_in[2];
    const float* Whh = (const float*)d_in[3];
    const float* bih = (const float*)d_in[4];
    const float* bhh = (const float*)d_in[5];
    const float* fcw = (const float*)d_in[6];
    const float* fcb = (const float*)d_in[7];
    const float* cw  = (const float*)d_in[8];
    const float* cb  = (const float*)d_in[9];

    lstm_kernel<<<NB / 2, 32>>>(x, Wih, Whh, bih, bhh);
    head_kernel<<<1, NB>>>(la, fcw, fcb, cw, cb, (float*)d_out);
}